// round 4
// baseline (speedup 1.0000x reference)
#include <cuda_runtime.h>
#include <cuda_bf16.h>

// ---------------------------------------------------------------------------
// SageConv: out = relu([x@Wl + bl | (scatter_sum(val*x[col] -> row))@Wn + bn])
// N=100000 nodes, E=1.6M edges, D_IN=D_OUT=128.
//
//   1) zero_kernel     : clear 51.2MB agg scratch
//   2) scatter_kernel  : persistent grid-stride, 8 edges in flight per warp,
//                        float4 gather + red.global.add.v4.f32 (L2-resident)
//   3) fused_kernel    : persistent CTAs, W in shared, fp32x2 packed FMA,
//                        streaming (evict-first) output stores
//   4) dummy_kernel    : shifts ncu's "-s 5" capture window onto the scatter
// ---------------------------------------------------------------------------

#define N_MAX_NODES 100000
#define D 128
#define TM 32  // rows per tile in fused gemm

__device__ __align__(16) float g_agg[N_MAX_NODES * D];

// ---------------------------------------------------------------------------
__global__ void zero_kernel(int n4) {
    float4* p = reinterpret_cast<float4*>(g_agg);
    float4 z = make_float4(0.f, 0.f, 0.f, 0.f);
    for (int i = blockIdx.x * blockDim.x + threadIdx.x; i < n4;
         i += gridDim.x * blockDim.x) {
        p[i] = z;
    }
}

__global__ void dummy_kernel() {}

// ---------------------------------------------------------------------------
__device__ __forceinline__ void red_add_v4(float* addr, float a, float b, float c, float d) {
    asm volatile("red.global.add.v4.f32 [%0], {%1, %2, %3, %4};"
                 :: "l"(addr), "f"(a), "f"(b), "f"(c), "f"(d)
                 : "memory");
}

// Persistent grid-stride scatter: each warp keeps EPW independent edge
// gathers in flight (batch index loads -> batch gathers -> batch REDs).
#define EPW 8  // edges in flight per warp

__global__ void __launch_bounds__(256)
scatter_kernel(const float4* __restrict__ x4,
               const int* __restrict__ erow,
               const int* __restrict__ ecol,
               const float* __restrict__ eval_,
               int E) {
    const int lane = threadIdx.x & 31;
    const int gwarp = (blockIdx.x * blockDim.x + threadIdx.x) >> 5;
    const int nwarps = (gridDim.x * blockDim.x) >> 5;

    for (int e0 = gwarp * EPW; e0 < E; e0 += nwarps * EPW) {
        const int cnt = min(EPW, E - e0);

        int r[EPW], c[EPW];
        float v[EPW];
#pragma unroll
        for (int i = 0; i < EPW; i++) {
            if (i < cnt) {
                r[i] = __ldg(erow + e0 + i);
                c[i] = __ldg(ecol + e0 + i);
                v[i] = __ldg(eval_ + e0 + i);
            }
        }

        float4 xv[EPW];
#pragma unroll
        for (int i = 0; i < EPW; i++) {
            if (i < cnt) xv[i] = __ldg(x4 + (size_t)c[i] * 32 + lane);
        }

#pragma unroll
        for (int i = 0; i < EPW; i++) {
            if (i < cnt) {
                float* dst = g_agg + (size_t)r[i] * D + lane * 4;
                red_add_v4(dst, xv[i].x * v[i], xv[i].y * v[i],
                                xv[i].z * v[i], xv[i].w * v[i]);
            }
        }
    }
}

// ---------------------------------------------------------------------------
// Packed fp32x2 FMA (sm_103a): d = a * b + d  (two fp32 lanes per instruction)
#define FMA2(d, a, b) \
    asm("fma.rn.f32x2 %0, %1, %2, %0;" : "+l"(d) : "l"(a), "l"(b))

__device__ __forceinline__ unsigned long long splat2(float v) {
    unsigned long long r;
    asm("mov.b64 %0, {%1, %1};" : "=l"(r) : "f"(v));
    return r;
}

__device__ __forceinline__ float2 unpack2(unsigned long long p) {
    float2 r;
    asm("mov.b64 {%0, %1}, %2;" : "=f"(r.x), "=f"(r.y) : "l"(p));
    return r;
}

// Shared layout (dynamic):
//   sW : 2 * 128 * 128 floats  (Wl then Wn), [k*128 + col]
//   sA : 2 * TM * 128 floats   (x tile then agg tile), [r*128 + k]
#define SMEM_FLOATS (2 * D * D + 2 * TM * D)
#define SMEM_BYTES  (SMEM_FLOATS * 4)

__global__ void __launch_bounds__(256)
fused_kernel(const float* __restrict__ x,
             const float* __restrict__ Wl,
             const float* __restrict__ bl,
             const float* __restrict__ Wn,
             const float* __restrict__ bn,
             float* __restrict__ out,
             int n) {
    extern __shared__ float sm[];
    float* sW = sm;                 // 32768 floats
    float* sA = sm + 2 * D * D;     // 8192 floats

    const int tid = threadIdx.x;

    // Load both weight matrices into shared (once per CTA; L2-resident)
    {
        const float4* wl4 = reinterpret_cast<const float4*>(Wl);
        const float4* wn4 = reinterpret_cast<const float4*>(Wn);
        float4* sW4 = reinterpret_cast<float4*>(sW);
        for (int i = tid; i < D * D / 4; i += 256) {
            sW4[i] = wl4[i];
            sW4[D * D / 4 + i] = wn4[i];
        }
    }

    // Thread mapping: warp w: half = w>>2 (0=local,1=neigh), rowgroup = w&3
    // lane covers 4 output cols: c0 = lane*4. Thread tile = 8 rows x 4 cols.
    const int lane = tid & 31;
    const int w = tid >> 5;
    const int half = w >> 2;
    const int rg = w & 3;
    const int r0 = rg * 8;
    const int c0 = lane * 4;

    const float* Wh = sW + half * (D * D);
    const float* bias = half ? bn : bl;
    float4 bb = *reinterpret_cast<const float4*>(bias + c0);

    const float4* x4 = reinterpret_cast<const float4*>(x);
    const float4* a4 = reinterpret_cast<const float4*>(g_agg);

    const int ntiles = (n + TM - 1) / TM;

    __syncthreads();

    for (int t = blockIdx.x; t < ntiles; t += gridDim.x) {
        const int row0 = t * TM;

        // Load x-tile and agg-tile (TM x 128 each) into shared
        {
            float4* sA4 = reinterpret_cast<float4*>(sA);
            float4 z = make_float4(0.f, 0.f, 0.f, 0.f);
            for (int i = tid; i < TM * (D / 4); i += 256) {
                int r = i >> 5;           // row within tile
                int kk = i & 31;          // float4 within row
                int gr = row0 + r;
                float4 vx = z, va = z;
                if (gr < n) {
                    vx = x4[(size_t)gr * 32 + kk];
                    va = a4[(size_t)gr * 32 + kk];
                }
                sA4[i] = vx;
                sA4[TM * (D / 4) + i] = va;
            }
        }
        __syncthreads();

        const float* Arow = sA + half * (TM * D) + r0 * D;

        unsigned long long acc[8][2];
#pragma unroll
        for (int r = 0; r < 8; r++) { acc[r][0] = 0ull; acc[r][1] = 0ull; }

        for (int k = 0; k < D; k += 4) {
            // preload 4 k-values for each of 8 rows (broadcast LDS.128)
            float4 xr[8];
#pragma unroll
            for (int r = 0; r < 8; r++)
                xr[r] = *reinterpret_cast<const float4*>(Arow + r * D + k);

#pragma unroll
            for (int kk = 0; kk < 4; kk++) {
                // W row: float4 load = two f32x2 operands for free
                ulonglong2 wv = *reinterpret_cast<const ulonglong2*>(
                    Wh + (k + kk) * D + c0);
#pragma unroll
                for (int r = 0; r < 8; r++) {
                    float xv = reinterpret_cast<const float*>(&xr[r])[kk];
                    unsigned long long xs = splat2(xv);
                    FMA2(acc[r][0], xs, wv.x);
                    FMA2(acc[r][1], xs, wv.y);
                }
            }
        }

        // Epilogue: bias + relu + concat, streaming store (don't pollute L2:
        // out is 102MB/replay and never re-read; keep x+agg resident instead)
#pragma unroll
        for (int r = 0; r < 8; r++) {
            int gr = row0 + r0 + r;
            if (gr < n) {
                float2 p0 = unpack2(acc[r][0]);
                float2 p1 = unpack2(acc[r][1]);
                float4 o;
                o.x = fmaxf(p0.x + bb.x, 0.f);
                o.y = fmaxf(p0.y + bb.y, 0.f);
                o.z = fmaxf(p1.x + bb.z, 0.f);
                o.w = fmaxf(p1.y + bb.w, 0.f);
                __stcs(reinterpret_cast<float4*>(out + (size_t)gr * 256 + half * D + c0), o);
            }
        }
        __syncthreads();
    }
}

// ---------------------------------------------------------------------------
extern "C" void kernel_launch(void* const* d_in, const int* in_sizes, int n_in,
                              void* d_out, int out_size) {
    const float* x  = (const float*)d_in[0];
    const int* erow = (const int*)d_in[1];
    const int* ecol = (const int*)d_in[2];
    const float* ev = (const float*)d_in[3];
    const float* Wl = (const float*)d_in[4];
    const float* bl = (const float*)d_in[5];
    const float* Wn = (const float*)d_in[6];
    const float* bn = (const float*)d_in[7];

    const int n = in_sizes[0] / D;   // nodes
    const int E = in_sizes[1];       // edges

    // 1) zero the agg scratch
    zero_kernel<<<2048, 256>>>(n * (D / 4));

    // 2) scatter: persistent grid-stride, 8 edges in flight per warp
    scatter_kernel<<<2048, 256>>>(
        reinterpret_cast<const float4*>(x), erow, ecol, ev, E);

    // 3) fused dual-GEMM + bias + relu + concat (persistent grid)
    cudaFuncSetAttribute(fused_kernel,
                         cudaFuncAttributeMaxDynamicSharedMemorySize, SMEM_BYTES);
    fused_kernel<<<148, 256, SMEM_BYTES>>>(x, Wl, bl, Wn, bn, (float*)d_out, n);

    // 4) dummy launch: makes 4 launches/call so ncu's "-s 5 -c 1" window
    //    (launch index 5) lands on the SECOND call's scatter_kernel.
    dummy_kernel<<<1, 32>>>();
}

// round 6
// speedup vs baseline: 1.1830x; 1.1830x over previous
#include <cuda_runtime.h>
#include <cuda_bf16.h>

// ---------------------------------------------------------------------------
// SageConv: out = relu([x@Wl + bl | (scatter_sum(val*x[col] -> row))@Wn + bn])
// N=100000 nodes, E=1.6M edges, D_IN=D_OUT=128.
//
// CSR build + pull-style SpMM (no atomics on feature data):
//   1) k_zero_deg   : zero degree counters
//   2) k_hist       : histogram edge rows
//   3) k_partial    : per-block degree sums
//   4) k_scan       : scan block partials (1 block, 512 threads; nb=391<=512)
//   5) k_offsets    : block-local scan + base -> row offsets + cursors
//   6) k_bin        : bin {col,val} pairs into CSR order (atomic cursor)
//   7) k_pull       : warp-per-row gather+accumulate in registers, 1 store
//   8) fused_kernel : dual-GEMM + bias + relu + concat (fp32x2 FMA)
// ---------------------------------------------------------------------------

#define NN 100000
#define EE 1600000
#define D 128
#define TM 32

__device__ __align__(16) float g_agg[NN * D];
__device__ int g_deg[NN];
__device__ int g_off[NN + 1];
__device__ int g_cur[NN];
__device__ int g_part[512];   // block partials; requires ceil(NN/256) <= 512
__device__ __align__(8) unsigned long long g_csr[EE];  // hi32=val bits, lo32=col

// ---------------------------------------------------------------------------
__global__ void k_zero_deg(int n) {
    for (int i = blockIdx.x * blockDim.x + threadIdx.x; i < n;
         i += gridDim.x * blockDim.x)
        g_deg[i] = 0;
}

__global__ void k_hist(const int* __restrict__ erow, int E) {
    for (int e = blockIdx.x * blockDim.x + threadIdx.x; e < E;
         e += gridDim.x * blockDim.x)
        atomicAdd(&g_deg[__ldg(erow + e)], 1);
}

__global__ void k_partial(int n) {
    __shared__ int s[256];
    int i = blockIdx.x * 256 + threadIdx.x;
    s[threadIdx.x] = (i < n) ? g_deg[i] : 0;
    __syncthreads();
    for (int d = 128; d > 0; d >>= 1) {
        if (threadIdx.x < d) s[threadIdx.x] += s[threadIdx.x + d];
        __syncthreads();
    }
    if (threadIdx.x == 0) g_part[blockIdx.x] = s[0];
}

__global__ void k_scan(int nb) {   // 1 block, 512 threads; nb <= 512
    __shared__ int s[512];
    int t = threadIdx.x;
    s[t] = (t < nb) ? g_part[t] : 0;
    __syncthreads();
    for (int d = 1; d < 512; d <<= 1) {
        int v = (t >= d) ? s[t - d] : 0;
        __syncthreads();
        s[t] += v;
        __syncthreads();
    }
    int excl = (t > 0) ? s[t - 1] : 0;
    if (t < nb) g_part[t] = excl;
}

__global__ void k_offsets(int n) {
    __shared__ int s[256];
    int t = threadIdx.x;
    int i = blockIdx.x * 256 + t;
    int dg = (i < n) ? g_deg[i] : 0;
    s[t] = dg;
    __syncthreads();
    for (int d = 1; d < 256; d <<= 1) {
        int v = (t >= d) ? s[t - d] : 0;
        __syncthreads();
        s[t] += v;
        __syncthreads();
    }
    int incl = s[t];
    int base = g_part[blockIdx.x];
    if (i < n) {
        int off = base + incl - dg;
        g_off[i] = off;
        g_cur[i] = off;
        if (i == n - 1) g_off[n] = base + incl;
    }
}

__global__ void k_bin(const int* __restrict__ erow,
                      const int* __restrict__ ecol,
                      const float* __restrict__ eval_, int E) {
    for (int e = blockIdx.x * blockDim.x + threadIdx.x; e < E;
         e += gridDim.x * blockDim.x) {
        int r = __ldg(erow + e);
        int c = __ldg(ecol + e);
        float v = __ldg(eval_ + e);
        int pos = atomicAdd(&g_cur[r], 1);
        g_csr[pos] = ((unsigned long long)__float_as_uint(v) << 32) | (unsigned)c;
    }
}

// Pull-style SpMM: one warp per row; accumulate val*x[col] in registers.
__global__ void __launch_bounds__(256)
k_pull(const float4* __restrict__ x4, int n) {
    const int lane = threadIdx.x & 31;
    const int gwarp = (blockIdx.x * blockDim.x + threadIdx.x) >> 5;
    const int nwarps = (gridDim.x * blockDim.x) >> 5;

    for (int r = gwarp; r < n; r += nwarps) {
        const int beg = __ldg(g_off + r);
        const int end = __ldg(g_off + r + 1);
        float4 acc = make_float4(0.f, 0.f, 0.f, 0.f);

        int j = beg;
        for (; j + 4 <= end; j += 4) {
            unsigned long long p0 = __ldg(g_csr + j);
            unsigned long long p1 = __ldg(g_csr + j + 1);
            unsigned long long p2 = __ldg(g_csr + j + 2);
            unsigned long long p3 = __ldg(g_csr + j + 3);
            float4 a = __ldg(x4 + (size_t)(unsigned)p0 * 32 + lane);
            float4 b = __ldg(x4 + (size_t)(unsigned)p1 * 32 + lane);
            float4 c = __ldg(x4 + (size_t)(unsigned)p2 * 32 + lane);
            float4 dd = __ldg(x4 + (size_t)(unsigned)p3 * 32 + lane);
            float v0 = __uint_as_float((unsigned)(p0 >> 32));
            float v1 = __uint_as_float((unsigned)(p1 >> 32));
            float v2 = __uint_as_float((unsigned)(p2 >> 32));
            float v3 = __uint_as_float((unsigned)(p3 >> 32));
            acc.x += v0 * a.x; acc.y += v0 * a.y; acc.z += v0 * a.z; acc.w += v0 * a.w;
            acc.x += v1 * b.x; acc.y += v1 * b.y; acc.z += v1 * b.z; acc.w += v1 * b.w;
            acc.x += v2 * c.x; acc.y += v2 * c.y; acc.z += v2 * c.z; acc.w += v2 * c.w;
            acc.x += v3 * dd.x; acc.y += v3 * dd.y; acc.z += v3 * dd.z; acc.w += v3 * dd.w;
        }
        for (; j < end; j++) {
            unsigned long long p = __ldg(g_csr + j);
            float4 a = __ldg(x4 + (size_t)(unsigned)p * 32 + lane);
            float v = __uint_as_float((unsigned)(p >> 32));
            acc.x += v * a.x; acc.y += v * a.y; acc.z += v * a.z; acc.w += v * a.w;
        }
        reinterpret_cast<float4*>(g_agg)[(size_t)r * 32 + lane] = acc;
    }
}

// ---------------------------------------------------------------------------
// Packed fp32x2 FMA (sm_103a): d = a * b + d
#define FMA2(d, a, b) \
    asm("fma.rn.f32x2 %0, %1, %2, %0;" : "+l"(d) : "l"(a), "l"(b))

__device__ __forceinline__ unsigned long long splat2(float v) {
    unsigned long long r;
    asm("mov.b64 %0, {%1, %1};" : "=l"(r) : "f"(v));
    return r;
}

__device__ __forceinline__ float2 unpack2(unsigned long long p) {
    float2 r;
    asm("mov.b64 {%0, %1}, %2;" : "=f"(r.x), "=f"(r.y) : "l"(p));
    return r;
}

#define SMEM_FLOATS (2 * D * D + 2 * TM * D)
#define SMEM_BYTES  (SMEM_FLOATS * 4)

__global__ void __launch_bounds__(256)
fused_kernel(const float* __restrict__ x,
             const float* __restrict__ Wl,
             const float* __restrict__ bl,
             const float* __restrict__ Wn,
             const float* __restrict__ bn,
             float* __restrict__ out,
             int n) {
    extern __shared__ float sm[];
    float* sW = sm;                 // 32768 floats
    float* sA = sm + 2 * D * D;     // 8192 floats

    const int tid = threadIdx.x;

    {
        const float4* wl4 = reinterpret_cast<const float4*>(Wl);
        const float4* wn4 = reinterpret_cast<const float4*>(Wn);
        float4* sW4 = reinterpret_cast<float4*>(sW);
        for (int i = tid; i < D * D / 4; i += 256) {
            sW4[i] = wl4[i];
            sW4[D * D / 4 + i] = wn4[i];
        }
    }

    const int lane = tid & 31;
    const int w = tid >> 5;
    const int half = w >> 2;
    const int rg = w & 3;
    const int r0 = rg * 8;
    const int c0 = lane * 4;

    const float* Wh = sW + half * (D * D);
    const float* bias = half ? bn : bl;
    float4 bb = *reinterpret_cast<const float4*>(bias + c0);

    const float4* x4 = reinterpret_cast<const float4*>(x);
    const float4* a4 = reinterpret_cast<const float4*>(g_agg);

    const int ntiles = (n + TM - 1) / TM;

    __syncthreads();

    for (int t = blockIdx.x; t < ntiles; t += gridDim.x) {
        const int row0 = t * TM;

        {
            float4* sA4 = reinterpret_cast<float4*>(sA);
            float4 z = make_float4(0.f, 0.f, 0.f, 0.f);
            for (int i = tid; i < TM * (D / 4); i += 256) {
                int r = i >> 5;
                int kk = i & 31;
                int gr = row0 + r;
                float4 vx = z, va = z;
                if (gr < n) {
                    vx = x4[(size_t)gr * 32 + kk];
                    va = a4[(size_t)gr * 32 + kk];
                }
                sA4[i] = vx;
                sA4[TM * (D / 4) + i] = va;
            }
        }
        __syncthreads();

        const float* Arow = sA + half * (TM * D) + r0 * D;

        unsigned long long acc[8][2];
#pragma unroll
        for (int r = 0; r < 8; r++) { acc[r][0] = 0ull; acc[r][1] = 0ull; }

        for (int k = 0; k < D; k += 4) {
            float4 xr[8];
#pragma unroll
            for (int r = 0; r < 8; r++)
                xr[r] = *reinterpret_cast<const float4*>(Arow + r * D + k);

#pragma unroll
            for (int kk = 0; kk < 4; kk++) {
                ulonglong2 wv = *reinterpret_cast<const ulonglong2*>(
                    Wh + (k + kk) * D + c0);
#pragma unroll
                for (int r = 0; r < 8; r++) {
                    float xv = reinterpret_cast<const float*>(&xr[r])[kk];
                    unsigned long long xs = splat2(xv);
                    FMA2(acc[r][0], xs, wv.x);
                    FMA2(acc[r][1], xs, wv.y);
                }
            }
        }

#pragma unroll
        for (int r = 0; r < 8; r++) {
            int gr = row0 + r0 + r;
            if (gr < n) {
                float2 p0 = unpack2(acc[r][0]);
                float2 p1 = unpack2(acc[r][1]);
                float4 o;
                o.x = fmaxf(p0.x + bb.x, 0.f);
                o.y = fmaxf(p0.y + bb.y, 0.f);
                o.z = fmaxf(p1.x + bb.z, 0.f);
                o.w = fmaxf(p1.y + bb.w, 0.f);
                __stcs(reinterpret_cast<float4*>(out + (size_t)gr * 256 + half * D + c0), o);
            }
        }
        __syncthreads();
    }
}

// ---------------------------------------------------------------------------
extern "C" void kernel_launch(void* const* d_in, const int* in_sizes, int n_in,
                              void* d_out, int out_size) {
    const float* x  = (const float*)d_in[0];
    const int* erow = (const int*)d_in[1];
    const int* ecol = (const int*)d_in[2];
    const float* ev = (const float*)d_in[3];
    const float* Wl = (const float*)d_in[4];
    const float* bl = (const float*)d_in[5];
    const float* Wn = (const float*)d_in[6];
    const float* bn = (const float*)d_in[7];

    const int n = in_sizes[0] / D;   // nodes (100000)
    const int E = in_sizes[1];       // edges (1600000)
    const int nb = (n + 255) / 256;  // 391 <= 512

    // CSR build (per call; no caching allowed)
    k_zero_deg<<<256, 256>>>(n);
    k_hist<<<1024, 256>>>(erow, E);
    k_partial<<<nb, 256>>>(n);
    k_scan<<<1, 512>>>(nb);
    k_offsets<<<nb, 256>>>(n);
    k_bin<<<1024, 256>>>(erow, ecol, ev, E);

    // Pull-style SpMM (register accumulation, no atomics on feature data)
    k_pull<<<2048, 256>>>(reinterpret_cast<const float4*>(x), n);

    // Fused dual-GEMM + bias + relu + concat (persistent grid)
    cudaFuncSetAttribute(fused_kernel,
                         cudaFuncAttributeMaxDynamicSharedMemorySize, SMEM_BYTES);
    fused_kernel<<<148, 256, SMEM_BYTES>>>(x, Wl, bl, Wn, bn, (float*)d_out, n);
}